// round 16
// baseline (speedup 1.0000x reference)
#include <cuda_runtime.h>
#include <math.h>

// Problem constants
#define Sx   128
#define Bx   32
#define Dx   512
#define Hx   512
#define G4x  2048   // 4*H
#define Vx   8000
#define SBx  4096   // S*B

#define NCTA      128   // persistent CTAs (<= SM count, 1/SM -> co-resident)
#define CTA_DIR   64    // CTAs per direction

// ---------------------------------------------------------------------------
// Device scratch (static globals: allocation-free)
// ---------------------------------------------------------------------------
__device__ float g_gates[2][(size_t)Sx * Bx * G4x];   // per-dir gate pre-activations (layer-reused)
__device__ float g_h0[2][(size_t)Sx * Bx * Hx];       // layer-0 hidden states (actual time order)
__device__ float g_h1[2][(size_t)Sx * Bx * Hx];       // layer-1 hidden states
__device__ unsigned g_cnt[2];                         // barrier arrival counters (per dir)
__device__ volatile unsigned g_gen[2];                // barrier generation (per dir)

// ---------------------------------------------------------------------------
// Generic fp32 GEMM:  O[M,N] = A[M,K] * W[N,K]^T + b1[n] (+ b2[n])
// BM=128, BN=128, BK=16, 256 threads, 8x8 register tile. (unchanged, proven)
// ---------------------------------------------------------------------------
__global__ __launch_bounds__(256) void gemm_bias(
    const float* __restrict__ Aext, int a_sel, long long a_off,
    const float* __restrict__ W,
    const float* __restrict__ b1, const float* __restrict__ b2,
    float* __restrict__ Oext, int o_sel, long long o_off,
    int M, int N, int K)
{
    __shared__ float As[16 * 128];
    __shared__ float Ws[16 * 128];

    const float* A = (a_sel == 0) ? Aext : ((a_sel == 1) ? &g_h0[0][0] : &g_h1[0][0]);
    A += a_off;
    float* O = (o_sel == 0) ? Oext : &g_gates[0][0];
    O += o_off;

    const int tid  = threadIdx.x;
    const int n0   = blockIdx.x * 128;
    const int m0   = blockIdx.y * 128;
    const int lr   = tid & 127;
    const int lk   = (tid >> 7) * 8;
    const int trow = tid >> 4;
    const int tcol = tid & 15;

    float acc[8][8];
#pragma unroll
    for (int i = 0; i < 8; i++)
#pragma unroll
        for (int j = 0; j < 8; j++) acc[i][j] = 0.f;

    for (int k0 = 0; k0 < K; k0 += 16) {
        const float* ap = A + (size_t)(m0 + lr) * K + k0 + lk;
        float4 a0 = *(const float4*)(ap);
        float4 a1 = *(const float4*)(ap + 4);
        float4 w0 = make_float4(0.f, 0.f, 0.f, 0.f), w1 = w0;
        if (n0 + lr < N) {
            const float* wp = W + (size_t)(n0 + lr) * K + k0 + lk;
            w0 = *(const float4*)(wp);
            w1 = *(const float4*)(wp + 4);
        }
        __syncthreads();
        As[(lk + 0) * 128 + lr] = a0.x;  As[(lk + 1) * 128 + lr] = a0.y;
        As[(lk + 2) * 128 + lr] = a0.z;  As[(lk + 3) * 128 + lr] = a0.w;
        As[(lk + 4) * 128 + lr] = a1.x;  As[(lk + 5) * 128 + lr] = a1.y;
        As[(lk + 6) * 128 + lr] = a1.z;  As[(lk + 7) * 128 + lr] = a1.w;
        Ws[(lk + 0) * 128 + lr] = w0.x;  Ws[(lk + 1) * 128 + lr] = w0.y;
        Ws[(lk + 2) * 128 + lr] = w0.z;  Ws[(lk + 3) * 128 + lr] = w0.w;
        Ws[(lk + 4) * 128 + lr] = w1.x;  Ws[(lk + 5) * 128 + lr] = w1.y;
        Ws[(lk + 6) * 128 + lr] = w1.z;  Ws[(lk + 7) * 128 + lr] = w1.w;
        __syncthreads();

#pragma unroll
        for (int k = 0; k < 16; k++) {
            float4 av0 = *(const float4*)&As[k * 128 + trow * 8];
            float4 av1 = *(const float4*)&As[k * 128 + trow * 8 + 4];
            float4 wv0 = *(const float4*)&Ws[k * 128 + tcol * 4];
            float4 wv1 = *(const float4*)&Ws[k * 128 + 64 + tcol * 4];
            float av[8] = {av0.x, av0.y, av0.z, av0.w, av1.x, av1.y, av1.z, av1.w};
            float wv[8] = {wv0.x, wv0.y, wv0.z, wv0.w, wv1.x, wv1.y, wv1.z, wv1.w};
#pragma unroll
            for (int i = 0; i < 8; i++)
#pragma unroll
                for (int j = 0; j < 8; j++) acc[i][j] += av[i] * wv[j];
        }
    }

    const int nA = n0 + tcol * 4;
    const int nB = n0 + 64 + tcol * 4;
    float4 bA = make_float4(0.f, 0.f, 0.f, 0.f), bB = bA;
    if (nA < N) {
        bA = *(const float4*)(b1 + nA);
        if (b2) { float4 t = *(const float4*)(b2 + nA); bA.x += t.x; bA.y += t.y; bA.z += t.z; bA.w += t.w; }
    }
    if (nB < N) {
        bB = *(const float4*)(b1 + nB);
        if (b2) { float4 t = *(const float4*)(b2 + nB); bB.x += t.x; bB.y += t.y; bB.z += t.z; bB.w += t.w; }
    }
#pragma unroll
    for (int i = 0; i < 8; i++) {
        size_t m = (size_t)(m0 + trow * 8 + i);
        if (nA < N) {
            float4 r = make_float4(acc[i][0] + bA.x, acc[i][1] + bA.y,
                                   acc[i][2] + bA.z, acc[i][3] + bA.w);
            *(float4*)(O + m * N + nA) = r;
        }
        if (nB < N) {
            float4 r = make_float4(acc[i][4] + bB.x, acc[i][5] + bB.y,
                                   acc[i][6] + bB.z, acc[i][7] + bB.w);
            *(float4*)(O + m * N + nB) = r;
        }
    }
}

// ---------------------------------------------------------------------------
// Persistent per-layer recurrence kernel.
// Grid = 128 CTAs (64 per direction), 256 threads. Each CTA owns 8 hidden
// units: jbase = (cta%64)*8 -> gate columns {g*512 + jbase + 0..7, g=0..3}.
// W_hh slice lives in registers (64 floats/thread). Cell state in registers.
// Per step: stage h_prev (64KB) + input gates into smem, k-split dot with
// shuffle reduce, LSTM cell, write h[t] to global, inter-CTA barrier per dir.
//
// Thread map (compute): kc = tid&15 (k-chunk of 32), cl = tid>>4 (col pair):
//   local cols lc0=2cl, lc1=2cl+1. Warp w covers local cols 4w..4w+3; the
//   16-lane shuffle reduce stays inside lane halves.
// Thread map (cell):    b = lane, jj = warp (8 warps -> 8 j's).
//
// SMEM (dynamic, 74240 B):
//   h_pad  : 16 chunks * (32b*32k + 4 skew) = 16*1028 floats (skew -> the
//            per-kc 128B-apart reads land on distinct banks per 8-lane phase)
//   gates_s: [32b][33] floats
//   res_s  : [32col][33] floats
// ---------------------------------------------------------------------------
#define LSTM_SMEM_FLOATS (16 * 1028 + 32 * 33 + 32 * 33)

__global__ __launch_bounds__(256) void lstm_layer(
    const float* __restrict__ Whf, const float* __restrict__ Whb, int layer_sel)
{
    extern __shared__ float smem[];
    float* h_pad   = smem;                 // 16*1028
    float* gates_s = smem + 16 * 1028;     // 32*33
    float* res_s   = gates_s + 32 * 33;    // 32*33

    const int cta   = blockIdx.x;
    const int dir   = cta >> 6;
    const int jbase = (cta & 63) * 8;
    const int tid   = threadIdx.x;
    const int lane  = tid & 31;
    const int w     = tid >> 5;
    const int kc    = tid & 15;
    const int cl    = tid >> 4;

    const float* W = dir ? Whb : Whf;
    float* hdir = (layer_sel ? &g_h1[0][0] : &g_h0[0][0]) + (size_t)dir * Sx * Bx * Hx;
    const float* gdir = &g_gates[dir][0];

    // ---- Load W_hh slice into registers: 2 cols x 32 k per thread ----
    const int lc0 = 2 * cl, lc1 = 2 * cl + 1;
    const int gc0 = ((lc0 >> 3) << 9) + jbase + (lc0 & 7);
    const int gc1 = ((lc1 >> 3) << 9) + jbase + (lc1 & 7);
    float4 w0r[8], w1r[8];
    {
        const float4* p0 = (const float4*)(W + (size_t)gc0 * Hx + kc * 32);
        const float4* p1 = (const float4*)(W + (size_t)gc1 * Hx + kc * 32);
#pragma unroll
        for (int i = 0; i < 8; i++) { w0r[i] = p0[i]; w1r[i] = p1[i]; }
    }

    float c_reg = 0.f;                 // cell state for cell (b=lane, jj=w)
    unsigned base = 0;
    if (tid == 0) base = g_gen[dir];   // read before any barrier can bump it

    for (int t = 0; t < Sx; t++) {
        const int tt = dir ? (Sx - 1 - t) : t;

        // ---- stage h_prev into skewed smem layout ----
        if (t > 0) {
            const int tp = dir ? (tt + 1) : (tt - 1);
            const float* hp = hdir + (size_t)tp * (Bx * Hx);
#pragma unroll
            for (int it = 0; it < 16; it++) {
                int idx = it * 256 + tid;           // 0..4095
                int b = idx >> 7, k4 = idx & 127;
                float4 v = *(const float4*)(hp + b * 512 + k4 * 4);
                int ck = k4 >> 3, i = k4 & 7;
                *(float4*)&h_pad[ck * 1028 + b * 32 + i * 4] = v;
            }
        } else {
#pragma unroll
            for (int it = 0; it < 16; it++) {
                int idx = it * 256 + tid;
                int b = idx >> 7, k4 = idx & 127;
                int ck = k4 >> 3, i = k4 & 7;
                *(float4*)&h_pad[ck * 1028 + b * 32 + i * 4] = make_float4(0.f, 0.f, 0.f, 0.f);
            }
        }
        // ---- stage input gates for this CTA's 32 columns ----
#pragma unroll
        for (int it = 0; it < 4; it++) {
            int idx = it * 256 + tid;               // 0..1023
            int b = idx >> 5, col = idx & 31;
            float v = gdir[((size_t)tt * Bx + b) * G4x + ((col >> 3) << 9) + jbase + (col & 7)];
            gates_s[b * 33 + col] = v;
        }
        __syncthreads();

        // ---- hidden GEMM: 2 cols x 32 k per thread, shuffle-reduce over kc ----
        const float* hck = h_pad + kc * 1028;
#pragma unroll 2
        for (int b = 0; b < 32; b++) {
            const float4* hp4 = (const float4*)(hck + b * 32);
            float s0a = 0.f, s0b = 0.f, s1a = 0.f, s1b = 0.f;
#pragma unroll
            for (int i = 0; i < 8; i += 2) {
                float4 h4 = hp4[i];
                float4 wa = w0r[i], wb = w1r[i];
                s0a += h4.x * wa.x; s0a += h4.y * wa.y; s0a += h4.z * wa.z; s0a += h4.w * wa.w;
                s1a += h4.x * wb.x; s1a += h4.y * wb.y; s1a += h4.z * wb.z; s1a += h4.w * wb.w;
                float4 h5 = hp4[i + 1];
                float4 wc = w0r[i + 1], wd = w1r[i + 1];
                s0b += h5.x * wc.x; s0b += h5.y * wc.y; s0b += h5.z * wc.z; s0b += h5.w * wc.w;
                s1b += h5.x * wd.x; s1b += h5.y * wd.y; s1b += h5.z * wd.z; s1b += h5.w * wd.w;
            }
            float r0 = s0a + s0b, r1 = s1a + s1b;
#pragma unroll
            for (int m = 8; m >= 1; m >>= 1) {
                r0 += __shfl_xor_sync(0xffffffffu, r0, m);
                r1 += __shfl_xor_sync(0xffffffffu, r1, m);
            }
            if ((lane & 15) == 0) {
                res_s[lc0 * 33 + b] = r0;
                res_s[lc1 * 33 + b] = r1;
            }
        }
        __syncthreads();

        // ---- LSTM cell: thread (b=lane, jj=w) ----
        {
            const int b = lane, jj = w;
            float gi = gates_s[b * 33 + jj]      + res_s[jj * 33 + b];
            float gf = gates_s[b * 33 + 8 + jj]  + res_s[(8 + jj) * 33 + b];
            float gg = gates_s[b * 33 + 16 + jj] + res_s[(16 + jj) * 33 + b];
            float go = gates_s[b * 33 + 24 + jj] + res_s[(24 + jj) * 33 + b];
            float is = 1.f / (1.f + expf(-gi));
            float fs = 1.f / (1.f + expf(-gf));
            float os = 1.f / (1.f + expf(-go));
            float gt = tanhf(gg);
            c_reg = fs * c_reg + is * gt;
            float hn = os * tanhf(c_reg);
            hdir[(size_t)tt * (Bx * Hx) + b * 512 + jbase + jj] = hn;
        }

        // ---- inter-CTA barrier (per direction) ----
        if (t < Sx - 1) {
            __threadfence();            // publish h writes (all threads, release)
            __syncthreads();
            if (tid == 0) {
                unsigned target = base + (unsigned)t + 1u;
                unsigned a = atomicAdd(&g_cnt[dir], 1u);
                if (a == CTA_DIR - 1) {
                    g_cnt[dir] = 0;
                    __threadfence();
                    g_gen[dir] = target;
                } else {
                    while ((int)(g_gen[dir] - target) < 0) { }
                    __threadfence();    // acquire
                }
            }
            __syncthreads();
        }
    }
}

// ---------------------------------------------------------------------------
// Host orchestration (graph-capturable: kernel launches only)
// ---------------------------------------------------------------------------
extern "C" void kernel_launch(void* const* d_in, const int* in_sizes, int n_in,
                              void* d_out, int out_size)
{
    (void)in_sizes; (void)n_in; (void)out_size;
    const float* x     = (const float*)d_in[0];
    const float* Wf_ih = (const float*)d_in[1];
    const float* Wf_hh = (const float*)d_in[2];
    const float* bf_ih = (const float*)d_in[3];
    const float* bf_hh = (const float*)d_in[4];
    const float* Wb_ih = (const float*)d_in[5];
    const float* Wb_hh = (const float*)d_in[6];
    const float* bb_ih = (const float*)d_in[7];
    const float* bb_hh = (const float*)d_in[8];
    const float* W_fwd = (const float*)d_in[9];
    const float* b_fwd = (const float*)d_in[10];
    const float* W_bwd = (const float*)d_in[11];
    const float* b_bwd = (const float*)d_in[12];
    float* out = (float*)d_out;

    const int lstm_smem = LSTM_SMEM_FLOATS * (int)sizeof(float);   // 74240 B
    cudaFuncSetAttribute(lstm_layer, cudaFuncAttributeMaxDynamicSharedMemorySize, lstm_smem);

    const dim3 gridL(16, 32);          // N=2048, M=4096
    const dim3 gridP(63, 32);          // N=8000 (ceil), M=4096
    const long long DIRG = (long long)Sx * Bx * G4x;   // per-dir gates stride
    const long long DIRH = (long long)Sx * Bx * Hx;    // per-dir h stride
    const long long WL1  = (long long)G4x * Hx;        // layer-1 weight offset

    // ---- Layer 0: input projections (biases folded in) ----
    gemm_bias<<<gridL, 256>>>(x, 0, 0, Wf_ih, bf_ih, bf_hh, nullptr, 1, 0,    SBx, G4x, Dx);
    gemm_bias<<<gridL, 256>>>(x, 0, 0, Wb_ih, bb_ih, bb_hh, nullptr, 1, DIRG, SBx, G4x, Dx);

    // ---- Layer 0: persistent recurrence (both dirs) ----
    lstm_layer<<<NCTA, 256, lstm_smem>>>(Wf_hh, Wb_hh, 0);

    // ---- Layer 1: input projections from layer-0 h ----
    gemm_bias<<<gridL, 256>>>(nullptr, 1, 0,    Wf_ih + WL1, bf_ih + G4x, bf_hh + G4x, nullptr, 1, 0,    SBx, G4x, Hx);
    gemm_bias<<<gridL, 256>>>(nullptr, 1, DIRH, Wb_ih + WL1, bb_ih + G4x, bb_hh + G4x, nullptr, 1, DIRG, SBx, G4x, Hx);

    // ---- Layer 1: persistent recurrence ----
    lstm_layer<<<NCTA, 256, lstm_smem>>>(Wf_hh + WL1, Wb_hh + WL1, 1);

    // ---- Output projections (fully overwrite d_out) ----
    gemm_bias<<<gridP, 256>>>(nullptr, 2, 0,    W_fwd, b_fwd, nullptr, out, 0, 0,                    SBx, Vx, Hx);
    gemm_bias<<<gridP, 256>>>(nullptr, 2, DIRH, W_bwd, b_bwd, nullptr, out, 0, (long long)SBx * Vx, SBx, Vx, Hx);
}

// round 17
// speedup vs baseline: 1.0010x; 1.0010x over previous
#include <cuda_runtime.h>
#include <math.h>

// Problem constants
#define Sx   128
#define Bx   32
#define Dx   512
#define Hx   512
#define G4x  2048   // 4*H
#define Vx   8000
#define SBx  4096   // S*B

#define NCTA      128   // persistent CTAs (<= SM count, 1/SM -> co-resident)
#define CTA_DIR   64    // CTAs per direction

// ---------------------------------------------------------------------------
// Device scratch (static globals: allocation-free)
// ---------------------------------------------------------------------------
__device__ float g_gates[2][(size_t)Sx * Bx * G4x];   // per-dir gate pre-activations (layer-reused)
__device__ float g_h0[2][(size_t)Sx * Bx * Hx];       // layer-0 hidden states (actual time order)
__device__ float g_h1[2][(size_t)Sx * Bx * Hx];       // layer-1 hidden states
__device__ unsigned g_cnt[2];                         // barrier arrival counters (per dir)
__device__ volatile unsigned g_gen[2];                // barrier generation (per dir)

// ---------------------------------------------------------------------------
// Generic fp32 GEMM:  O[M,N] = A[M,K] * W[N,K]^T + b1[n] (+ b2[n])
// BM=128, BN=128, BK=16, 256 threads, 8x8 register tile. (unchanged, proven)
// ---------------------------------------------------------------------------
__global__ __launch_bounds__(256) void gemm_bias(
    const float* __restrict__ Aext, int a_sel, long long a_off,
    const float* __restrict__ W,
    const float* __restrict__ b1, const float* __restrict__ b2,
    float* __restrict__ Oext, int o_sel, long long o_off,
    int M, int N, int K)
{
    __shared__ float As[16 * 128];
    __shared__ float Ws[16 * 128];

    const float* A = (a_sel == 0) ? Aext : ((a_sel == 1) ? &g_h0[0][0] : &g_h1[0][0]);
    A += a_off;
    float* O = (o_sel == 0) ? Oext : &g_gates[0][0];
    O += o_off;

    const int tid  = threadIdx.x;
    const int n0   = blockIdx.x * 128;
    const int m0   = blockIdx.y * 128;
    const int lr   = tid & 127;
    const int lk   = (tid >> 7) * 8;
    const int trow = tid >> 4;
    const int tcol = tid & 15;

    float acc[8][8];
#pragma unroll
    for (int i = 0; i < 8; i++)
#pragma unroll
        for (int j = 0; j < 8; j++) acc[i][j] = 0.f;

    for (int k0 = 0; k0 < K; k0 += 16) {
        const float* ap = A + (size_t)(m0 + lr) * K + k0 + lk;
        float4 a0 = *(const float4*)(ap);
        float4 a1 = *(const float4*)(ap + 4);
        float4 w0 = make_float4(0.f, 0.f, 0.f, 0.f), w1 = w0;
        if (n0 + lr < N) {
            const float* wp = W + (size_t)(n0 + lr) * K + k0 + lk;
            w0 = *(const float4*)(wp);
            w1 = *(const float4*)(wp + 4);
        }
        __syncthreads();
        As[(lk + 0) * 128 + lr] = a0.x;  As[(lk + 1) * 128 + lr] = a0.y;
        As[(lk + 2) * 128 + lr] = a0.z;  As[(lk + 3) * 128 + lr] = a0.w;
        As[(lk + 4) * 128 + lr] = a1.x;  As[(lk + 5) * 128 + lr] = a1.y;
        As[(lk + 6) * 128 + lr] = a1.z;  As[(lk + 7) * 128 + lr] = a1.w;
        Ws[(lk + 0) * 128 + lr] = w0.x;  Ws[(lk + 1) * 128 + lr] = w0.y;
        Ws[(lk + 2) * 128 + lr] = w0.z;  Ws[(lk + 3) * 128 + lr] = w0.w;
        Ws[(lk + 4) * 128 + lr] = w1.x;  Ws[(lk + 5) * 128 + lr] = w1.y;
        Ws[(lk + 6) * 128 + lr] = w1.z;  Ws[(lk + 7) * 128 + lr] = w1.w;
        __syncthreads();

#pragma unroll
        for (int k = 0; k < 16; k++) {
            float4 av0 = *(const float4*)&As[k * 128 + trow * 8];
            float4 av1 = *(const float4*)&As[k * 128 + trow * 8 + 4];
            float4 wv0 = *(const float4*)&Ws[k * 128 + tcol * 4];
            float4 wv1 = *(const float4*)&Ws[k * 128 + 64 + tcol * 4];
            float av[8] = {av0.x, av0.y, av0.z, av0.w, av1.x, av1.y, av1.z, av1.w};
            float wv[8] = {wv0.x, wv0.y, wv0.z, wv0.w, wv1.x, wv1.y, wv1.z, wv1.w};
#pragma unroll
            for (int i = 0; i < 8; i++)
#pragma unroll
                for (int j = 0; j < 8; j++) acc[i][j] += av[i] * wv[j];
        }
    }

    const int nA = n0 + tcol * 4;
    const int nB = n0 + 64 + tcol * 4;
    float4 bA = make_float4(0.f, 0.f, 0.f, 0.f), bB = bA;
    if (nA < N) {
        bA = *(const float4*)(b1 + nA);
        if (b2) { float4 t = *(const float4*)(b2 + nA); bA.x += t.x; bA.y += t.y; bA.z += t.z; bA.w += t.w; }
    }
    if (nB < N) {
        bB = *(const float4*)(b1 + nB);
        if (b2) { float4 t = *(const float4*)(b2 + nB); bB.x += t.x; bB.y += t.y; bB.z += t.z; bB.w += t.w; }
    }
#pragma unroll
    for (int i = 0; i < 8; i++) {
        size_t m = (size_t)(m0 + trow * 8 + i);
        if (nA < N) {
            float4 r = make_float4(acc[i][0] + bA.x, acc[i][1] + bA.y,
                                   acc[i][2] + bA.z, acc[i][3] + bA.w);
            *(float4*)(O + m * N + nA) = r;
        }
        if (nB < N) {
            float4 r = make_float4(acc[i][4] + bB.x, acc[i][5] + bB.y,
                                   acc[i][6] + bB.z, acc[i][7] + bB.w);
            *(float4*)(O + m * N + nB) = r;
        }
    }
}

// ---------------------------------------------------------------------------
// Persistent per-layer recurrence kernel.
// Grid = 128 CTAs (64 per direction), 256 threads. Each CTA owns 8 hidden
// units: jbase = (cta%64)*8 -> gate columns {g*512 + jbase + 0..7, g=0..3}.
// W_hh slice lives in registers (64 floats/thread). Cell state in registers.
// Per step: stage h_prev (64KB) + input gates into smem, k-split dot with
// shuffle reduce, LSTM cell, write h[t] to global, inter-CTA barrier per dir.
//
// Thread map (compute): kc = tid&15 (k-chunk of 32), cl = tid>>4 (col pair):
//   local cols lc0=2cl, lc1=2cl+1. Warp w covers local cols 4w..4w+3; the
//   16-lane shuffle reduce stays inside lane halves.
// Thread map (cell):    b = lane, jj = warp (8 warps -> 8 j's).
//
// SMEM (dynamic, 74240 B):
//   h_pad  : 16 chunks * (32b*32k + 4 skew) = 16*1028 floats (skew -> the
//            per-kc 128B-apart reads land on distinct banks per 8-lane phase)
//   gates_s: [32b][33] floats
//   res_s  : [32col][33] floats
// ---------------------------------------------------------------------------
#define LSTM_SMEM_FLOATS (16 * 1028 + 32 * 33 + 32 * 33)

__global__ __launch_bounds__(256) void lstm_layer(
    const float* __restrict__ Whf, const float* __restrict__ Whb, int layer_sel)
{
    extern __shared__ float smem[];
    float* h_pad   = smem;                 // 16*1028
    float* gates_s = smem + 16 * 1028;     // 32*33
    float* res_s   = gates_s + 32 * 33;    // 32*33

    const int cta   = blockIdx.x;
    const int dir   = cta >> 6;
    const int jbase = (cta & 63) * 8;
    const int tid   = threadIdx.x;
    const int lane  = tid & 31;
    const int w     = tid >> 5;
    const int kc    = tid & 15;
    const int cl    = tid >> 4;

    const float* W = dir ? Whb : Whf;
    float* hdir = (layer_sel ? &g_h1[0][0] : &g_h0[0][0]) + (size_t)dir * Sx * Bx * Hx;
    const float* gdir = &g_gates[dir][0];

    // ---- Load W_hh slice into registers: 2 cols x 32 k per thread ----
    const int lc0 = 2 * cl, lc1 = 2 * cl + 1;
    const int gc0 = ((lc0 >> 3) << 9) + jbase + (lc0 & 7);
    const int gc1 = ((lc1 >> 3) << 9) + jbase + (lc1 & 7);
    float4 w0r[8], w1r[8];
    {
        const float4* p0 = (const float4*)(W + (size_t)gc0 * Hx + kc * 32);
        const float4* p1 = (const float4*)(W + (size_t)gc1 * Hx + kc * 32);
#pragma unroll
        for (int i = 0; i < 8; i++) { w0r[i] = p0[i]; w1r[i] = p1[i]; }
    }

    float c_reg = 0.f;                 // cell state for cell (b=lane, jj=w)
    unsigned base = 0;
    if (tid == 0) base = g_gen[dir];   // read before any barrier can bump it

    for (int t = 0; t < Sx; t++) {
        const int tt = dir ? (Sx - 1 - t) : t;

        // ---- stage h_prev into skewed smem layout ----
        if (t > 0) {
            const int tp = dir ? (tt + 1) : (tt - 1);
            const float* hp = hdir + (size_t)tp * (Bx * Hx);
#pragma unroll
            for (int it = 0; it < 16; it++) {
                int idx = it * 256 + tid;           // 0..4095
                int b = idx >> 7, k4 = idx & 127;
                float4 v = *(const float4*)(hp + b * 512 + k4 * 4);
                int ck = k4 >> 3, i = k4 & 7;
                *(float4*)&h_pad[ck * 1028 + b * 32 + i * 4] = v;
            }
        } else {
#pragma unroll
            for (int it = 0; it < 16; it++) {
                int idx = it * 256 + tid;
                int b = idx >> 7, k4 = idx & 127;
                int ck = k4 >> 3, i = k4 & 7;
                *(float4*)&h_pad[ck * 1028 + b * 32 + i * 4] = make_float4(0.f, 0.f, 0.f, 0.f);
            }
        }
        // ---- stage input gates for this CTA's 32 columns ----
#pragma unroll
        for (int it = 0; it < 4; it++) {
            int idx = it * 256 + tid;               // 0..1023
            int b = idx >> 5, col = idx & 31;
            float v = gdir[((size_t)tt * Bx + b) * G4x + ((col >> 3) << 9) + jbase + (col & 7)];
            gates_s[b * 33 + col] = v;
        }
        __syncthreads();

        // ---- hidden GEMM: 2 cols x 32 k per thread, shuffle-reduce over kc ----
        const float* hck = h_pad + kc * 1028;
#pragma unroll 2
        for (int b = 0; b < 32; b++) {
            const float4* hp4 = (const float4*)(hck + b * 32);
            float s0a = 0.f, s0b = 0.f, s1a = 0.f, s1b = 0.f;
#pragma unroll
            for (int i = 0; i < 8; i += 2) {
                float4 h4 = hp4[i];
                float4 wa = w0r[i], wb = w1r[i];
                s0a += h4.x * wa.x; s0a += h4.y * wa.y; s0a += h4.z * wa.z; s0a += h4.w * wa.w;
                s1a += h4.x * wb.x; s1a += h4.y * wb.y; s1a += h4.z * wb.z; s1a += h4.w * wb.w;
                float4 h5 = hp4[i + 1];
                float4 wc = w0r[i + 1], wd = w1r[i + 1];
                s0b += h5.x * wc.x; s0b += h5.y * wc.y; s0b += h5.z * wc.z; s0b += h5.w * wc.w;
                s1b += h5.x * wd.x; s1b += h5.y * wd.y; s1b += h5.z * wd.z; s1b += h5.w * wd.w;
            }
            float r0 = s0a + s0b, r1 = s1a + s1b;
#pragma unroll
            for (int m = 8; m >= 1; m >>= 1) {
                r0 += __shfl_xor_sync(0xffffffffu, r0, m);
                r1 += __shfl_xor_sync(0xffffffffu, r1, m);
            }
            if ((lane & 15) == 0) {
                res_s[lc0 * 33 + b] = r0;
                res_s[lc1 * 33 + b] = r1;
            }
        }
        __syncthreads();

        // ---- LSTM cell: thread (b=lane, jj=w) ----
        {
            const int b = lane, jj = w;
            float gi = gates_s[b * 33 + jj]      + res_s[jj * 33 + b];
            float gf = gates_s[b * 33 + 8 + jj]  + res_s[(8 + jj) * 33 + b];
            float gg = gates_s[b * 33 + 16 + jj] + res_s[(16 + jj) * 33 + b];
            float go = gates_s[b * 33 + 24 + jj] + res_s[(24 + jj) * 33 + b];
            float is = 1.f / (1.f + expf(-gi));
            float fs = 1.f / (1.f + expf(-gf));
            float os = 1.f / (1.f + expf(-go));
            float gt = tanhf(gg);
            c_reg = fs * c_reg + is * gt;
            float hn = os * tanhf(c_reg);
            hdir[(size_t)tt * (Bx * Hx) + b * 512 + jbase + jj] = hn;
        }

        // ---- inter-CTA barrier (per direction) ----
        if (t < Sx - 1) {
            __threadfence();            // publish h writes (all threads, release)
            __syncthreads();
            if (tid == 0) {
                unsigned target = base + (unsigned)t + 1u;
                unsigned a = atomicAdd(&g_cnt[dir], 1u);
                if (a == CTA_DIR - 1) {
                    g_cnt[dir] = 0;
                    __threadfence();
                    g_gen[dir] = target;
                } else {
                    while ((int)(g_gen[dir] - target) < 0) { }
                    __threadfence();    // acquire
                }
            }
            __syncthreads();
        }
    }
}

// ---------------------------------------------------------------------------
// Host orchestration (graph-capturable: kernel launches only)
// ---------------------------------------------------------------------------
extern "C" void kernel_launch(void* const* d_in, const int* in_sizes, int n_in,
                              void* d_out, int out_size)
{
    (void)in_sizes; (void)n_in; (void)out_size;
    const float* x     = (const float*)d_in[0];
    const float* Wf_ih = (const float*)d_in[1];
    const float* Wf_hh = (const float*)d_in[2];
    const float* bf_ih = (const float*)d_in[3];
    const float* bf_hh = (const float*)d_in[4];
    const float* Wb_ih = (const float*)d_in[5];
    const float* Wb_hh = (const float*)d_in[6];
    const float* bb_ih = (const float*)d_in[7];
    const float* bb_hh = (const float*)d_in[8];
    const float* W_fwd = (const float*)d_in[9];
    const float* b_fwd = (const float*)d_in[10];
    const float* W_bwd = (const float*)d_in[11];
    const float* b_bwd = (const float*)d_in[12];
    float* out = (float*)d_out;

    const int lstm_smem = LSTM_SMEM_FLOATS * (int)sizeof(float);   // 74240 B
    cudaFuncSetAttribute(lstm_layer, cudaFuncAttributeMaxDynamicSharedMemorySize, lstm_smem);

    const dim3 gridL(16, 32);          // N=2048, M=4096
    const dim3 gridP(63, 32);          // N=8000 (ceil), M=4096
    const long long DIRG = (long long)Sx * Bx * G4x;   // per-dir gates stride
    const long long DIRH = (long long)Sx * Bx * Hx;    // per-dir h stride
    const long long WL1  = (long long)G4x * Hx;        // layer-1 weight offset

    // ---- Layer 0: input projections (biases folded in) ----
    gemm_bias<<<gridL, 256>>>(x, 0, 0, Wf_ih, bf_ih, bf_hh, nullptr, 1, 0,    SBx, G4x, Dx);
    gemm_bias<<<gridL, 256>>>(x, 0, 0, Wb_ih, bb_ih, bb_hh, nullptr, 1, DIRG, SBx, G4x, Dx);

    // ---- Layer 0: persistent recurrence (both dirs) ----
    lstm_layer<<<NCTA, 256, lstm_smem>>>(Wf_hh, Wb_hh, 0);

    // ---- Layer 1: input projections from layer-0 h ----
    gemm_bias<<<gridL, 256>>>(nullptr, 1, 0,    Wf_ih + WL1, bf_ih + G4x, bf_hh + G4x, nullptr, 1, 0,    SBx, G4x, Hx);
    gemm_bias<<<gridL, 256>>>(nullptr, 1, DIRH, Wb_ih + WL1, bb_ih + G4x, bb_hh + G4x, nullptr, 1, DIRG, SBx, G4x, Hx);

    // ---- Layer 1: persistent recurrence ----
    lstm_layer<<<NCTA, 256, lstm_smem>>>(Wf_hh + WL1, Wb_hh + WL1, 1);

    // ---- Output projections (fully overwrite d_out) ----
    gemm_bias<<<gridP, 256>>>(nullptr, 2, 0,    W_fwd, b_fwd, nullptr, out, 0, 0,                    SBx, Vx, Hx);
    gemm_bias<<<gridP, 256>>>(nullptr, 2, DIRH, W_bwd, b_bwd, nullptr, out, 0, (long long)SBx * Vx, SBx, Vx, Hx);
}